// round 11
// baseline (speedup 1.0000x reference)
#include <cuda_runtime.h>

#define B_    64
#define CIN   512
#define COUT  512
#define HW    784      // 28*28
#define FAN   513      // CIN + 1 (rate column)
#define KSEL  256      // K = COUT * 0.5
#define RATE  0.5f

#define K1_BLOCKS 888                  // 148 SMs x 6 resident blocks
#define K1_WARPS  (K1_BLOCKS * 8)      // 7104 warps
#define NROWS     (B_ * CIN)           // 32768

// Scratch (allocation-free rule: __device__ globals)
__device__ float d_s_scr[B_ * CIN];    // per-(b,c) mean |x|
__device__ float d_g_scr[B_ * COUT];   // gate values after relu
// Per-batch-group completion counters. Never reset: each launch adds exactly
// 8 per group, so (old & 7) == 7 identifies the 8th finisher of THIS launch.
// Deterministic across graph replays.
__device__ unsigned d_cnt[16];

// ---------------------------------------------------------------------------
// Kernel 1: s[b,c] = mean(|x[b,c,:,:]|). Best-measured persistent config
// (R6: 19.58us): 888 blocks, lb(256,6), grid-stride one row per warp-iter,
// plain LDG float4 body. Staggered drain -> PDL dependent overlaps cleanly.
// ---------------------------------------------------------------------------
__global__ void __launch_bounds__(256, 6) k1_absmean(const float* __restrict__ x) {
    int w    = blockIdx.x * 8 + (threadIdx.x >> 5);
    int lane = threadIdx.x & 31;
    const float4* xb = reinterpret_cast<const float4*>(x);

    for (int row = w; row < NROWS; row += K1_WARPS) {
        const float4* p = xb + (size_t)row * 196;
        float acc = 0.f;
        #pragma unroll
        for (int i = 0; i < 7; i++) {
            int idx = lane + i * 32;
            if (idx < 196) {
                float4 v = p[idx];
                acc += fabsf(v.x) + fabsf(v.y) + fabsf(v.z) + fabsf(v.w);
            }
        }
        #pragma unroll
        for (int o = 16; o; o >>= 1) acc += __shfl_xor_sync(0xffffffffu, acc, o);
        if (lane == 0) d_s_scr[row] = acc * (1.0f / (float)HW);
    }
    cudaTriggerProgrammaticLaunchCompletion();
}

// ---------------------------------------------------------------------------
// Kernel 2 (FUSED): gate GEMM + last-block radix-select + renormalize.
// Grid (16,8): block = 4 batches x 64 channels, identical GEMM to before.
// After storing its tile each block arrives on its group's counter; the 8th
// finisher selects+renormalizes the group's 4 rows in-block (128 thr/row,
// 4 rows concurrent). Eliminates the k3 launch entirely.
// ---------------------------------------------------------------------------
#define W_TILE_FLOATS (64 * FAN)            // 32832
#define S_STRIDE      520
#define K2_SMEM_BYTES ((W_TILE_FLOATS + 4 * S_STRIDE) * 4)

extern __shared__ float k2_smem[];

__global__ void k2_fused(const float* __restrict__ W, const float* __restrict__ bias,
                         float* __restrict__ out) {
    float* W_sm = k2_smem;                       // [64][513] flat
    float* s_sm = k2_smem + W_TILE_FLOATS;       // [4][520]
    int tid = threadIdx.x;
    int b0  = blockIdx.x * 4;
    int c0  = blockIdx.y * 64;

    // ---- prologue (independent of k1): stage W tile ----
    {
        const float4* wsrc = reinterpret_cast<const float4*>(W + (size_t)c0 * FAN);
        float4* wdst = reinterpret_cast<float4*>(W_sm);
        #pragma unroll 4
        for (int i = tid; i < W_TILE_FLOATS / 4; i += 512) wdst[i] = wsrc[i];
    }

    cudaGridDependencySynchronize();

    for (int idx = tid; idx < 4 * FAN; idx += 512) {
        int bb = idx / FAN, k = idx - bb * FAN;
        s_sm[bb * S_STRIDE + k] = (k < CIN) ? d_s_scr[(b0 + bb) * CIN + k] : RATE;
    }
    __syncthreads();

    int warp = tid >> 5, lane = tid & 31;
    int cl = warp * 4;
    float acc[4][4];
    #pragma unroll
    for (int bb = 0; bb < 4; bb++)
        #pragma unroll
        for (int cc = 0; cc < 4; cc++) acc[bb][cc] = 0.f;

    #pragma unroll 4
    for (int k = lane; k < FAN; k += 32) {
        float wv[4], sv[4];
        #pragma unroll
        for (int cc = 0; cc < 4; cc++) wv[cc] = W_sm[(cl + cc) * FAN + k];
        #pragma unroll
        for (int bb = 0; bb < 4; bb++) sv[bb] = s_sm[bb * S_STRIDE + k];
        #pragma unroll
        for (int bb = 0; bb < 4; bb++)
            #pragma unroll
            for (int cc = 0; cc < 4; cc++) acc[bb][cc] += wv[cc] * sv[bb];
    }
    #pragma unroll
    for (int o = 16; o; o >>= 1)
        #pragma unroll
        for (int bb = 0; bb < 4; bb++)
            #pragma unroll
            for (int cc = 0; cc < 4; cc++)
                acc[bb][cc] += __shfl_xor_sync(0xffffffffu, acc[bb][cc], o);

    if (lane == 0) {
        #pragma unroll
        for (int cc = 0; cc < 4; cc++) {
            float bv = bias[c0 + cl + cc];
            #pragma unroll
            for (int bb = 0; bb < 4; bb++)
                d_g_scr[(b0 + bb) * COUT + c0 + cl + cc] = fmaxf(acc[bb][cc] + bv, 0.f);
        }
    }
    __syncthreads();

    // ---- last-block-done detection ----
    __shared__ int s_last;
    if (tid == 0) {
        __threadfence();                              // publish g stores
        unsigned old = atomicAdd(&d_cnt[blockIdx.x], 1u);
        s_last = ((old & 7u) == 7u) ? 1 : 0;
    }
    __syncthreads();
    if (!s_last) { cudaTriggerProgrammaticLaunchCompletion(); return; }

    // =======================================================================
    // Selection + renormalize for rows b0..b0+3. 4 groups x 128 threads,
    // group `sub` handles row b0+sub; thread tidg owns channels
    // [4*tidg, 4*tidg+4) (float4-coalesced; channel-ascending tie order).
    // =======================================================================
    __shared__ unsigned hist[4][256];
    __shared__ unsigned shd[4], shc[4];
    __shared__ unsigned wpref[16];
    __shared__ float    swsum[16];

    int sub  = tid >> 7;          // 0..3 row group
    int tidg = tid & 127;         // 0..127 within group
    int row  = b0 + sub;

    float4 gv = __ldcg(reinterpret_cast<const float4*>(d_g_scr + row * COUT) + tidg);
    float    gf[4] = { gv.x, gv.y, gv.z, gv.w };
    unsigned kk[4];
    #pragma unroll
    for (int j = 0; j < 4; j++) kk[j] = __float_as_uint(gf[j]);   // g>=0 monotone

    unsigned prefix = 0, mask = 0;
    unsigned target = KSEL - 1;
    unsigned countless = 0;
    unsigned* hflat = &hist[0][0];

    #pragma unroll
    for (int shift = 24; shift >= 0; shift -= 8) {
        hflat[tid] = 0; hflat[tid + 512] = 0;
        __syncthreads();
        #pragma unroll
        for (int j = 0; j < 4; j++)
            if ((kk[j] & mask) == prefix)
                atomicAdd(&hist[sub][(kk[j] >> shift) & 255u], 1u);
        __syncthreads();

        if (tidg < 32) {          // one scan-warp per row group
            unsigned s = 0;
            #pragma unroll
            for (int k = 0; k < 8; k++) s += hist[sub][lane * 8 + k];
            unsigned incl = s;
            #pragma unroll
            for (int o = 1; o < 32; o <<= 1) {
                unsigned t = __shfl_up_sync(0xffffffffu, incl, o);
                if (lane >= o) incl += t;
            }
            unsigned excl = incl - s;
            if (excl <= target && target < incl) {
                unsigned cum = excl;
                unsigned d = lane * 8;
                #pragma unroll
                for (int k = 0; k < 8; k++) {
                    unsigned h = hist[sub][lane * 8 + k];
                    if (cum + h > target) { d = lane * 8 + k; break; }
                    cum += h;
                }
                shd[sub] = d;
                shc[sub] = cum;
            }
        }
        __syncthreads();
        unsigned cb = shc[sub], dg = shd[sub];
        target    -= cb;
        countless += cb;
        prefix |= dg << shift;
        mask   |= 0xFFu << shift;
        __syncthreads();
    }

    unsigned tau = prefix;
    unsigned E = KSEL - countless;            // # tau-equal elements to zero

    // per-thread eq count + exclusive prefix over the 128-thread group
    unsigned localcnt = 0;
    #pragma unroll
    for (int j = 0; j < 4; j++) localcnt += (kk[j] == tau);
    unsigned inc = localcnt;
    #pragma unroll
    for (int o = 1; o < 32; o <<= 1) {
        unsigned t = __shfl_up_sync(0xffffffffu, inc, o);
        if (lane >= o) inc += t;
    }
    if (lane == 31) wpref[warp] = inc;        // warp totals (16 warps)
    __syncthreads();
    unsigned woff = 0;
    #pragma unroll
    for (int w = 0; w < 4; w++) {
        int wi = sub * 4 + w;
        woff += (wi < warp) ? wpref[wi] : 0u;
    }
    unsigned myExcl = woff + (inc - localcnt);

    float t[4]; float part = 0.f; unsigned cum = 0;
    #pragma unroll
    for (int j = 0; j < 4; j++) {
        bool eq = (kk[j] == tau);
        unsigned off = myExcl + cum;
        bool zero = (kk[j] < tau) || (eq && off < E);
        t[j] = zero ? 0.f : gf[j];
        part += t[j];
        cum += eq;
    }

    // row sum across group's 4 warps
    #pragma unroll
    for (int o = 16; o; o >>= 1) part += __shfl_xor_sync(0xffffffffu, part, o);
    if (lane == 0) swsum[warp] = part;
    __syncthreads();
    float tot = swsum[sub * 4] + swsum[sub * 4 + 1] +
                swsum[sub * 4 + 2] + swsum[sub * 4 + 3];
    float scale = (float)COUT / tot;

    reinterpret_cast<float4*>(out + row * COUT)[tidg] =
        make_float4(t[0] * scale, t[1] * scale, t[2] * scale, t[3] * scale);
    cudaTriggerProgrammaticLaunchCompletion();
}

// ---------------------------------------------------------------------------
extern "C" void kernel_launch(void* const* d_in, const int* in_sizes, int n_in,
                              void* d_out, int out_size) {
    const float* x    = (const float*)d_in[0];
    const float* W    = (const float*)d_in[1];
    const float* bias = (const float*)d_in[2];
    float* out = (float*)d_out;

    cudaFuncSetAttribute(k2_fused, cudaFuncAttributeMaxDynamicSharedMemorySize,
                         K2_SMEM_BYTES);

    k1_absmean<<<K1_BLOCKS, 256>>>(x);

    // fused gate+select with Programmatic Dependent Launch
    {
        cudaLaunchConfig_t cfg = {};
        cfg.gridDim  = dim3(16, 8);
        cfg.blockDim = dim3(512);
        cfg.dynamicSmemBytes = K2_SMEM_BYTES;
        cfg.stream = 0;
        cudaLaunchAttribute at[1];
        at[0].id = cudaLaunchAttributeProgrammaticStreamSerialization;
        at[0].val.programmaticStreamSerializationAllowed = 1;
        cfg.attrs = at;
        cfg.numAttrs = 1;
        cudaLaunchKernelEx(&cfg, k2_fused, W, bias, out);
    }
}